// round 12
// baseline (speedup 1.0000x reference)
#include <cuda_runtime.h>
#include <cstdint>

#define N_NODES 50000
#define N_EDGES 400000
#define N_PATHS 512
#define DIM 64
#define QMAGIC 8388608.0f  // 2^23 mantissa-rounding trick

// ---------------- device scratch (static: no runtime allocation) ----------------
__device__ float g_deg[N_NODES];
__device__ float g_agg0[N_NODES * DIM];
__device__ float g_agg1[N_NODES * DIM];
__device__ float g_h0[N_NODES * DIM];
__device__ float g_h1[N_NODES * DIM];
__device__ float g_path[N_PATHS * DIM];
__device__ int   g_is32;
__device__ int   g_maxh[2];   // [0]: max|h1| bits, [1]: dummy for layer0

// ---------------- common helpers ----------------
__device__ __forceinline__ unsigned f2tf32(float f) {
    unsigned u;
    asm("cvt.rna.tf32.f32 %0, %1;" : "=r"(u) : "f"(f));
    return u;
}

__device__ __forceinline__ void mma8(float* c, const unsigned* a, unsigned b0, unsigned b1) {
    asm volatile(
        "mma.sync.aligned.m16n8k8.row.col.f32.tf32.tf32.f32 "
        "{%0,%1,%2,%3}, {%4,%5,%6,%7}, {%8,%9}, {%0,%1,%2,%3};"
        : "+f"(c[0]), "+f"(c[1]), "+f"(c[2]), "+f"(c[3])
        : "r"(a[0]), "r"(a[1]), "r"(a[2]), "r"(a[3]), "r"(b0), "r"(b1));
}

__device__ __forceinline__ void imma32(int* c, unsigned a0, unsigned a1,
                                       unsigned a2, unsigned a3,
                                       unsigned b0, unsigned b1) {
    asm volatile(
        "mma.sync.aligned.m16n8k32.row.col.s32.s8.s8.s32 "
        "{%0,%1,%2,%3}, {%4,%5,%6,%7}, {%8,%9}, {%0,%1,%2,%3};"
        : "+r"(c[0]), "+r"(c[1]), "+r"(c[2]), "+r"(c[3])
        : "r"(a0), "r"(a1), "r"(a2), "r"(a3), "r"(b0), "r"(b1));
}

__device__ __forceinline__ void cp16(float* sdst, const float* gsrc) {
    unsigned s = (unsigned)__cvta_generic_to_shared(sdst);
    asm volatile("cp.async.cg.shared.global [%0], [%1], 16;" ::"r"(s), "l"(gsrc));
}

// quantize 4 consecutive fp32 (already in [0,127] after scaling) to packed s8 word
__device__ __forceinline__ unsigned q4pack(float x, float y, float z, float w,
                                           float scale) {
    unsigned t0 = __float_as_uint(fmaf(x, scale, QMAGIC));
    unsigned t1 = __float_as_uint(fmaf(y, scale, QMAGIC));
    unsigned t2 = __float_as_uint(fmaf(z, scale, QMAGIC));
    unsigned t3 = __float_as_uint(fmaf(w, scale, QMAGIC));
    unsigned w1 = __byte_perm(t0, t1, 0x0040);
    unsigned w2 = __byte_perm(t2, t3, 0x0040);
    return __byte_perm(w1, w2, 0x5410);
}

// on-the-fly edge index fetch (handles int32 or int64 payload)
__device__ __forceinline__ void load_edge(const void* ei, int flag, int e,
                                          int& s, int& d) {
    if (flag) {
        const int* p = (const int*)ei;
        s = __ldg(&p[e]);
        d = __ldg(&p[N_EDGES + e]);
    } else {
        const long long* p = (const long long*)ei;
        s = (int)__ldg(&p[e]);
        d = (int)__ldg(&p[N_EDGES + e]);
    }
}

// ---------------- launch 1: fused init (zero scratch) + dtype probe (block 0) ----------------
__global__ void init_kernel(float* __restrict__ deg, float* __restrict__ agg0,
                            float* __restrict__ agg1, float* __restrict__ pemb,
                            int* __restrict__ flag, int* __restrict__ maxh,
                            const int* __restrict__ ei_w) {
    int i = blockIdx.x * blockDim.x + threadIdx.x;
    if (i < N_NODES) deg[i] = 0.0f;
    if (i < N_NODES * DIM) { agg0[i] = 0.0f; agg1[i] = 0.0f; }
    if (i < N_PATHS * DIM) pemb[i] = 0.0f;
    if (i < 2) maxh[i] = 0;
    if (blockIdx.x == 0) {
        int t = threadIdx.x;
        int nz = 0;
#pragma unroll
        for (int k = 0; k < 16; k++) {
            int idx = t * 16 + k;
            if (ei_w[2 * idx + 1] != 0) nz = 1;
        }
        int any = __syncthreads_or(nz);
        if (t == 0) *flag = any;
    }
}

// ---------------- scatter-sum: agg[dst] += x[src]; optional degree count ----------------
template <bool WITH_DEG>
__global__ void scatter_kernel(const float* __restrict__ x,
                               const void* __restrict__ ei,
                               const int* __restrict__ flagp,
                               float* __restrict__ agg,
                               float* __restrict__ deg) {
    int idx = blockIdx.x * blockDim.x + threadIdx.x;
    if (idx >= N_EDGES * 16) return;
    int e = idx >> 4;
    int j = idx & 15;
    int flag = *flagp;
    int s, d;
    load_edge(ei, flag, e, s, d);
    if (WITH_DEG && j == 0) atomicAdd(&deg[d], 1.0f);
    float4 v = __ldg((const float4*)x + (size_t)s * 16 + j);
    atomicAdd((float4*)agg + (size_t)d * 16 + j, v);
}

// ---------------- SAGE layer via tf32 mma + fused max(h) ----------------
#define SAGE_AX_STRIDE 132
#define SAGE_W_STRIDE 72
#define SAGE_SMEM_BYTES ((128 * SAGE_AX_STRIDE + 128 * SAGE_W_STRIDE) * 4)

__global__ void __launch_bounds__(256) sage_mma_kernel(
    const float* __restrict__ agg, const float* __restrict__ deg,
    const float* __restrict__ x, const float* __restrict__ Wl,
    const float* __restrict__ Wr, const float* __restrict__ bl,
    float* __restrict__ h, int* __restrict__ maxbits) {
    extern __shared__ float sm[];
    float* sAX = sm;
    float* sW  = sm + 128 * SAGE_AX_STRIDE;

    int tid = threadIdx.x;
    int lane = tid & 31;
    int warp = tid >> 5;

    for (int i = tid; i < 1024; i += 256) {
        int k = i >> 4, c4 = i & 15;
        float4 wl = ((const float4*)Wl)[i];
        float4 wr = ((const float4*)Wr)[i];
        *(float4*)&sW[k * SAGE_W_STRIDE + c4 * 4] = wl;
        *(float4*)&sW[(k + 64) * SAGE_W_STRIDE + c4 * 4] = wr;
    }

    int bc = (lane & 3) * 2;
    float bias0[8], bias1[8];
#pragma unroll
    for (int ni = 0; ni < 8; ni++) {
        bias0[ni] = __ldg(&bl[ni * 8 + bc]);
        bias1[ni] = __ldg(&bl[ni * 8 + bc + 1]);
    }

    float hmax = 0.0f;
    int ntiles = (N_NODES + 127) / 128;
    for (int t = blockIdx.x; t < ntiles; t += gridDim.x) {
        int base = t * 128;
        __syncthreads();
        for (int i = tid; i < 2048; i += 256) {
            int r = i >> 4, c4 = i & 15;
            int row = base + r;
            float4 va = make_float4(0.f, 0.f, 0.f, 0.f);
            float4 vx = va;
            if (row < N_NODES) {
                va = ((const float4*)agg)[(size_t)row * 16 + c4];
                float iv = 1.0f / fmaxf(deg[row], 1.0f);
                va.x *= iv; va.y *= iv; va.z *= iv; va.w *= iv;
                vx = ((const float4*)x)[(size_t)row * 16 + c4];
            }
            *(float4*)&sAX[r * SAGE_AX_STRIDE + c4 * 4] = va;
            *(float4*)&sAX[r * SAGE_AX_STRIDE + 64 + c4 * 4] = vx;
        }
        __syncthreads();

        float acc[8][4];
#pragma unroll
        for (int ni = 0; ni < 8; ni++) {
            acc[ni][0] = bias0[ni];
            acc[ni][1] = bias1[ni];
            acc[ni][2] = bias0[ni];
            acc[ni][3] = bias1[ni];
        }

        int rb = warp * 16 + (lane >> 2);
        int nb = lane >> 2;
#pragma unroll
        for (int kk = 0; kk < 128; kk += 8) {
            int kA = kk + (lane & 3);
            unsigned a[4];
            a[0] = f2tf32(sAX[rb * SAGE_AX_STRIDE + kA]);
            a[1] = f2tf32(sAX[(rb + 8) * SAGE_AX_STRIDE + kA]);
            a[2] = f2tf32(sAX[rb * SAGE_AX_STRIDE + kA + 4]);
            a[3] = f2tf32(sAX[(rb + 8) * SAGE_AX_STRIDE + kA + 4]);
#pragma unroll
            for (int ni = 0; ni < 8; ni++) {
                unsigned b0 = f2tf32(sW[kA * SAGE_W_STRIDE + ni * 8 + nb]);
                unsigned b1 = f2tf32(sW[(kA + 4) * SAGE_W_STRIDE + ni * 8 + nb]);
                mma8(acc[ni], a, b0, b1);
            }
        }

        int r0 = base + rb;
#pragma unroll
        for (int ni = 0; ni < 8; ni++) {
            int col = ni * 8 + bc;
            if (r0 < N_NODES) {
                float2 o = make_float2(fmaxf(acc[ni][0], 0.f), fmaxf(acc[ni][1], 0.f));
                hmax = fmaxf(hmax, fmaxf(o.x, o.y));
                *(float2*)&h[(size_t)r0 * 64 + col] = o;
            }
            if (r0 + 8 < N_NODES) {
                float2 o = make_float2(fmaxf(acc[ni][2], 0.f), fmaxf(acc[ni][3], 0.f));
                hmax = fmaxf(hmax, fmaxf(o.x, o.y));
                *(float2*)&h[(size_t)(r0 + 8) * 64 + col] = o;
            }
        }
    }

    // fused global max(h) (positive floats: int compare is order-preserving)
#pragma unroll
    for (int off = 16; off > 0; off >>= 1)
        hmax = fmaxf(hmax, __shfl_xor_sync(0xffffffffu, hmax, off));
    if (lane == 0) atomicMax(maxbits, __float_as_int(hmax));
}

// ---------------- big GEMM: int8 IMMA m16n8k32, split-K, M-split (2 CTAs/SM) ----------------
// path_emb[512,64] += path_masks[512,K] @ B[K,64], B[k,:] = (h1[src[k]]+h1[dst[k]])*0.5
// A: fp32 in smem (cp.async), fragments quantized in regs (mantissa trick + prmt).
// B: fp32 staged [e][n], quantized+transposed to s8 [n][k-pack] tile per chunk.
#define SA_ROWS 256
#define SA_STRIDE 36
#define SA_FLOATS (SA_ROWS * SA_STRIDE)    // 9216 floats / buffer
#define ST_STRIDE 68                        // fp32 stage [32 e][64 n + pad]
#define ST_FLOATS (32 * ST_STRIDE)          // 2176
#define BQ_WSTRIDE 12                       // u32 words per n-row (8 data + 4 pad)
#define OFF_ST1 (2 * SA_FLOATS)             // 18432
#define OFF_ST2 (OFF_ST1 + ST_FLOATS)       // 20608
#define OFF_BQ  (OFF_ST2 + ST_FLOATS)       // 22784 (float offset; used as u32*)
#define GEMM_SMEM_BYTES ((OFF_BQ + 64 * BQ_WSTRIDE) * 4)   // 94208

__device__ __forceinline__ void load_chunk_A(float* sA, const float* __restrict__ A,
                                             int k0, int tid) {
    // 256 rows x 32 k = 2048 float4, 256 threads -> 8 each
#pragma unroll
    for (int i = 0; i < 8; i++) {
        int f = i * 256 + tid;
        int row = f >> 3;
        int c4 = f & 7;
        cp16(sA + row * SA_STRIDE + c4 * 4,
             A + (size_t)row * N_EDGES + k0 + c4 * 4);
    }
}

// async-gather both endpoint rows of 32 edges into st1/st2 ([e][n] fp32)
__device__ __forceinline__ void gather_stage(float* st1, float* st2,
                                             const float* __restrict__ h1,
                                             const void* __restrict__ ei,
                                             int flag, int k0, int tid) {
#pragma unroll
    for (int i = 0; i < 2; i++) {
        int f = i * 256 + tid;
        int e = f >> 4;
        int j = f & 15;
        int s, d;
        load_edge(ei, flag, k0 + e, s, d);
        cp16(st1 + e * ST_STRIDE + j * 4, h1 + (size_t)s * 64 + j * 4);
        cp16(st2 + e * ST_STRIDE + j * 4, h1 + (size_t)d * 64 + j * 4);
    }
}

// quantize stage -> s8 tile [n][k-pack] (threads 0..127: 4 edges x 4 n each)
__device__ __forceinline__ void quantize_B(const float* st1, const float* st2,
                                           unsigned* bq, int tid, float sE) {
    if (tid >= 128) return;
    int ep = tid & 7;          // edge group: edges 4ep..4ep+3
    int n0 = (tid >> 3) * 4;   // n range
    float4 t[4];
#pragma unroll
    for (int i = 0; i < 4; i++) {
        int e = 4 * ep + i;
        float4 a = *(const float4*)&st1[e * ST_STRIDE + n0];
        float4 b = *(const float4*)&st2[e * ST_STRIDE + n0];
        t[i] = make_float4(a.x + b.x, a.y + b.y, a.z + b.z, a.w + b.w);
    }
    // word for column n0+c packs edges 4ep..4ep+3
    unsigned w0 = q4pack(t[0].x, t[1].x, t[2].x, t[3].x, sE);
    unsigned w1 = q4pack(t[0].y, t[1].y, t[2].y, t[3].y, sE);
    unsigned w2 = q4pack(t[0].z, t[1].z, t[2].z, t[3].z, sE);
    unsigned w3 = q4pack(t[0].w, t[1].w, t[2].w, t[3].w, sE);
    bq[(n0 + 0) * BQ_WSTRIDE + ep] = w0;
    bq[(n0 + 1) * BQ_WSTRIDE + ep] = w1;
    bq[(n0 + 2) * BQ_WSTRIDE + ep] = w2;
    bq[(n0 + 3) * BQ_WSTRIDE + ep] = w3;
}

__global__ void __launch_bounds__(256, 2) path_gemm_kernel(
    const float* __restrict__ A, const float* __restrict__ h1,
    const void* __restrict__ ei, const int* __restrict__ flagp,
    const int* __restrict__ maxbits, float* __restrict__ C) {
    extern __shared__ float sm[];
    float* bufA[2] = {sm, sm + SA_FLOATS};
    float* st1 = sm + OFF_ST1;
    float* st2 = sm + OFF_ST2;
    unsigned* bq = (unsigned*)(sm + OFF_BQ);

    int tid = threadIdx.x;
    int lane = tid & 31;
    int warp = tid >> 5;
    int m0 = warp * 32;                 // 8 warps x 32 rows (local)
    int gid = lane >> 2;
    int tig = lane & 3;
    int flag = *flagp;

    float maxH = fmaxf(__int_as_float(*maxbits), 1e-10f);
    float sE = 0.5f * 127.0f / maxH;        // quantizer for (h_s + h_d)
    float fscale = maxH / (127.0f * 127.0f); // dequant for acc

    int kslice = blockIdx.x >> 1;       // 0..147
    int mbase = (blockIdx.x & 1) * 256; // M half
    const float* Am = A + (size_t)mbase * N_EDGES;

    const int nch = N_EDGES / 32;  // 12500
    int c0 = (int)(((long long)kslice * nch) / 148);
    int c1 = (int)(((long long)(kslice + 1) * nch) / 148);

    int acc[2][8][4] = {};

    // prologue: stage chunk c0
    load_chunk_A(bufA[0], Am, c0 * 32, tid);
    gather_stage(st1, st2, h1, ei, flag, c0 * 32, tid);
    asm volatile("cp.async.commit_group;");
    asm volatile("cp.async.wait_group 0;");
    __syncthreads();

    int buf = 0;
    for (int c = c0; c < c1; ++c) {
        // build s8 B tile for chunk c from the stage
        quantize_B(st1, st2, bq, tid, sE);
        __syncthreads();

        bool more = (c + 1 < c1);
        if (more) {
            load_chunk_A(bufA[buf ^ 1], Am, (c + 1) * 32, tid);
            gather_stage(st1, st2, h1, ei, flag, (c + 1) * 32, tid);
            asm volatile("cp.async.commit_group;");
        }

        // ---- compute chunk c: one k32 IMMA step ----
        const float* cA = bufA[buf];
        unsigned a[2][4];
#pragma unroll
        for (int mt = 0; mt < 2; mt++) {
            int r = m0 + gid + mt * 16;
            const float4 v0 = *(const float4*)&cA[r * SA_STRIDE + 4 * tig];
            const float4 v1 = *(const float4*)&cA[(r + 8) * SA_STRIDE + 4 * tig];
            const float4 v2 = *(const float4*)&cA[r * SA_STRIDE + 16 + 4 * tig];
            const float4 v3 = *(const float4*)&cA[(r + 8) * SA_STRIDE + 16 + 4 * tig];
            a[mt][0] = q4pack(v0.x, v0.y, v0.z, v0.w, 127.0f);
            a[mt][1] = q4pack(v1.x, v1.y, v1.z, v1.w, 127.0f);
            a[mt][2] = q4pack(v2.x, v2.y, v2.z, v2.w, 127.0f);
            a[mt][3] = q4pack(v3.x, v3.y, v3.z, v3.w, 127.0f);
        }
#pragma unroll
        for (int ni = 0; ni < 8; ni++) {
            unsigned b0 = bq[(ni * 8 + gid) * BQ_WSTRIDE + tig];
            unsigned b1 = bq[(ni * 8 + gid) * BQ_WSTRIDE + tig + 4];
            imma32(acc[0][ni], a[0][0], a[0][1], a[0][2], a[0][3], b0, b1);
            imma32(acc[1][ni], a[1][0], a[1][1], a[1][2], a[1][3], b0, b1);
        }

        if (more) asm volatile("cp.async.wait_group 0;");
        __syncthreads();
        buf ^= 1;
    }

    // epilogue: dequant + accumulate C with vector L2 reductions
#pragma unroll
    for (int mt = 0; mt < 2; mt++) {
        int row = mbase + m0 + mt * 16 + gid;
#pragma unroll
        for (int ni = 0; ni < 8; ni++) {
            int col = ni * 8 + 2 * tig;
            atomicAdd((float2*)&C[row * 64 + col],
                      make_float2(acc[mt][ni][0] * fscale, acc[mt][ni][1] * fscale));
            atomicAdd((float2*)&C[(row + 8) * 64 + col],
                      make_float2(acc[mt][ni][2] * fscale, acc[mt][ni][3] * fscale));
        }
    }
}

// ---------------- readout: out = path_emb @ Wro + bro ----------------
__global__ void readout_kernel(const float* __restrict__ P,
                               const float* __restrict__ W,
                               const float* __restrict__ b,
                               float* __restrict__ out) {
    int p = blockIdx.x;
    int d = threadIdx.x;
    float s = __ldg(&b[d]);
    const float* pr = P + p * 64;
#pragma unroll 16
    for (int k = 0; k < 64; k++) s += __ldg(&pr[k]) * __ldg(&W[k * 64 + d]);
    out[p * 64 + d] = s;
}

// ---------------- launcher ----------------
extern "C" void kernel_launch(void* const* d_in, const int* in_sizes, int n_in,
                              void* d_out, int out_size) {
    (void)in_sizes; (void)n_in; (void)out_size;
    const float* x   = (const float*)d_in[0];
    const void*  ei  = d_in[1];
    const float* pm  = (const float*)d_in[2];
    const float* Wl0 = (const float*)d_in[3];
    const float* Wr0 = (const float*)d_in[4];
    const float* bl0 = (const float*)d_in[5];
    const float* Wl1 = (const float*)d_in[6];
    const float* Wr1 = (const float*)d_in[7];
    const float* bl1 = (const float*)d_in[8];
    const float* Wro = (const float*)d_in[9];
    const float* bro = (const float*)d_in[10];
    float* out       = (float*)d_out;

    float *deg, *agg0, *agg1, *h0, *h1, *pemb;
    int *flag, *maxh;
    cudaGetSymbolAddress((void**)&deg,  g_deg);
    cudaGetSymbolAddress((void**)&agg0, g_agg0);
    cudaGetSymbolAddress((void**)&agg1, g_agg1);
    cudaGetSymbolAddress((void**)&h0,   g_h0);
    cudaGetSymbolAddress((void**)&h1,   g_h1);
    cudaGetSymbolAddress((void**)&pemb, g_path);
    cudaGetSymbolAddress((void**)&flag, g_is32);
    cudaGetSymbolAddress((void**)&maxh, g_maxh);

    cudaFuncSetAttribute(path_gemm_kernel,
                         cudaFuncAttributeMaxDynamicSharedMemorySize, GEMM_SMEM_BYTES);
    cudaFuncSetAttribute(sage_mma_kernel,
                         cudaFuncAttributeMaxDynamicSharedMemorySize, SAGE_SMEM_BYTES);

    // 1: fused zero/init + dtype probe
    init_kernel<<<(N_NODES * DIM + 255) / 256, 256>>>(deg, agg0, agg1, pemb, flag,
                                                      maxh, (const int*)ei);
    // 2: layer-0 scatter (+degree)
    scatter_kernel<true><<<(N_EDGES * 16 + 255) / 256, 256>>>(x, ei, flag, agg0, deg);
    // 3: layer-0 sage (max written to dummy slot)
    sage_mma_kernel<<<391, 256, SAGE_SMEM_BYTES>>>(agg0, deg, x, Wl0, Wr0, bl0, h0,
                                                   maxh + 1);
    // 4: layer-1 scatter
    scatter_kernel<false><<<(N_EDGES * 16 + 255) / 256, 256>>>(h0, ei, flag, agg1, deg);
    // 5: layer-1 sage (computes max|h1| for int8 scale)
    sage_mma_kernel<<<391, 256, SAGE_SMEM_BYTES>>>(agg1, deg, h0, Wl1, Wr1, bl1, h1,
                                                   maxh);
    // 6: big split-K GEMM (int8 IMMA)
    path_gemm_kernel<<<296, 256, GEMM_SMEM_BYTES>>>(pm, h1, ei, flag, maxh, pemb);
    // 7: readout
    readout_kernel<<<N_PATHS, 64>>>(pemb, Wro, bro, out);
}